// round 14
// baseline (speedup 1.0000x reference)
#include <cuda_runtime.h>
#include <cuda_bf16.h>
#include <cstdint>

// Fused gamma-pdf-weighted MSE mean reduction — warp-specialized TMA
// producer/consumer pipeline (no block barriers in the hot loop).
//
// mean( 0.5*(output-target)^2 * ef(target) )
// ef(y) = (BETA - c)*(1 - pdf(y)/FX_MAX) + c; pdf/FX_MAX < 4e-19 for fp32
// uniform targets except exact zeros -> log/exp only in cold branch.
//
// R14: warp-issued loads equilibrate at ~5.1 TB/s under every variation.
// B300_MICROARCH measured the TMA path at the full chip cap (~6300 B/cyc).
// R5's TMA attempt was bubble-bound (2 stages + per-tile __syncthreads).
// This version: dedicated producer warp, 6-stage ring, per-stage full/empty
// mbarriers (empty count = 7 consumer warps), producer runs NSTG ahead.

#define NBLK   592            // 148 SMs * 4
#define NTH    256            // warps 0-6 consume, warp 7 produces
#define NCONS  7              // consumer warps
#define TILE_F 896            // floats per stream per tile (= 224 lanes * 4)
#define TILE_B (TILE_F * 4)   // 3584 bytes
#define NSTG   6              // ring depth: 6 * 2 * 3584 = 43008 B smem

__device__ float        g_part[NBLK];
__device__ unsigned int g_count;   // zero-init; self-resetting via atomicInc wrap

// ---------------- math ----------------
__device__ __forceinline__ float elem_val(float o, float y) {
    const float A1        = -0.9355570857535674f;            // EST_A - 1
    const float NEG_LOC   = 1.1328205299926424e-27f;         // -EST_LOC
    const float INV_SCALE = (float)(1.0 / 1.5376362609160314);
    const float C0        = -58.4492351f;                    // -lgamma(a)-ln(scale)-ln(FX_MAX)
    const float C         = (float)(1.0 / 107.2185);
    const float BC        = 5.0f - (float)(1.0 / 107.2185);

    float r = 0.0f;
    if (y < 1e-6f) {                      // cold path: only (near-)zero targets
        float x  = (y + NEG_LOC) * INV_SCALE;
        float lp = fmaf(A1, __logf(x), C0) - x;
        r = __expf(lp);
    }
    float ef   = fmaf(BC, 1.0f - r, C);
    float diff = o - y;
    return 0.5f * diff * diff * ef;
}

__device__ __forceinline__ float quad_val(float4 o, float4 t) {
    return elem_val(o.x, t.x) + elem_val(o.y, t.y)
         + elem_val(o.z, t.z) + elem_val(o.w, t.w);
}

// ---------------- PTX helpers ----------------
__device__ __forceinline__ uint32_t smem_u32(const void* p) {
    uint32_t a;
    asm("{ .reg .u64 t; cvta.to.shared.u64 t, %1; cvt.u32.u64 %0, t; }"
        : "=r"(a) : "l"(p));
    return a;
}
__device__ __forceinline__ void mbar_init(uint32_t mbar, uint32_t count) {
    asm volatile("mbarrier.init.shared.b64 [%0], %1;"
                 :: "r"(mbar), "r"(count) : "memory");
}
__device__ __forceinline__ void mbar_expect_tx(uint32_t mbar, uint32_t bytes) {
    asm volatile("mbarrier.arrive.expect_tx.shared.b64 _, [%0], %1;"
                 :: "r"(mbar), "r"(bytes) : "memory");
}
__device__ __forceinline__ void mbar_arrive(uint32_t mbar) {
    asm volatile("mbarrier.arrive.shared.b64 _, [%0];"
                 :: "r"(mbar) : "memory");
}
// acquire wait — consumers (generic smem reads follow)
__device__ __forceinline__ void mbar_wait_acq(uint32_t mbar, uint32_t parity) {
    uint32_t done;
    do {
        asm volatile(
            "{ .reg .pred p;\n"
            "  mbarrier.try_wait.parity.acquire.cta.shared::cta.b64 p, [%1], %2, 0x989680;\n"
            "  selp.b32 %0, 1, 0, p; }"
            : "=r"(done) : "r"(mbar), "r"(parity) : "memory");
    } while (!done);
}
// relaxed wait — producer (post-wait accesses are async-proxy only)
__device__ __forceinline__ void mbar_wait_rlx(uint32_t mbar, uint32_t parity) {
    uint32_t done;
    do {
        asm volatile(
            "{ .reg .pred p;\n"
            "  mbarrier.try_wait.parity.relaxed.cta.shared::cta.b64 p, [%1], %2, 0x989680;\n"
            "  selp.b32 %0, 1, 0, p; }"
            : "=r"(done) : "r"(mbar), "r"(parity) : "memory");
    } while (!done);
}
__device__ __forceinline__ void bulk_ld(uint32_t dst, const float* src,
                                        uint32_t bytes, uint32_t mbar) {
    asm volatile(
        "cp.async.bulk.shared::cluster.global.mbarrier::complete_tx::bytes "
        "[%0], [%1], %2, [%3];"
        :: "r"(dst), "l"(src), "r"(bytes), "r"(mbar) : "memory");
}
__device__ __forceinline__ void fence_proxy_async_shared() {
    asm volatile("fence.proxy.async.shared::cta;" ::: "memory");
}

// ---------------- kernel ----------------
__global__ __launch_bounds__(NTH) void loss_tma_ws_kernel(
    const float* __restrict__ out, const float* __restrict__ tgt,
    float* __restrict__ result, int n)
{
    __shared__ alignas(16) float    s_o[NSTG][TILE_F];
    __shared__ alignas(16) float    s_t[NSTG][TILE_F];
    __shared__ alignas(8)  uint64_t s_full[NSTG];
    __shared__ alignas(8)  uint64_t s_empty[NSTG];
    __shared__ float s_warp[NTH / 32];
    __shared__ bool  s_last;

    const int tid  = threadIdx.x;
    const int lane = tid & 31;
    const int warp = tid >> 5;
    const int bid  = blockIdx.x;
    const int G    = gridDim.x;

    const int ntiles = n / TILE_F;
    const int cnt    = (bid < ntiles) ? (ntiles - bid + G - 1) / G : 0;

    if (tid == 0) {
        #pragma unroll
        for (int s = 0; s < NSTG; ++s) {
            mbar_init(smem_u32(&s_full[s]),  1);      // one expect_tx arrive
            mbar_init(smem_u32(&s_empty[s]), NCONS);  // one per consumer warp
        }
        fence_proxy_async_shared();
    }
    __syncthreads();     // barriers initialized before any use

    float sum = 0.0f;

    if (warp == NCONS) {
        // ================= producer (warp 7, lane 0) =====================
        if (lane == 0) {
            int s = 0, ph = 1;             // phase-1 cursor: first NSTG
            for (int kp = 0; kp < cnt; ++kp) {   // empty-waits pass instantly
                mbar_wait_rlx(smem_u32(&s_empty[s]), (uint32_t)ph);
                const size_t gk = (size_t)(bid + (long long)kp * G) * TILE_F;
                uint32_t fb = smem_u32(&s_full[s]);
                mbar_expect_tx(fb, 2 * TILE_B);
                bulk_ld(smem_u32(&s_o[s][0]), out + gk, TILE_B, fb);
                bulk_ld(smem_u32(&s_t[s][0]), tgt + gk, TILE_B, fb);
                if (++s == NSTG) { s = 0; ph ^= 1; }
            }
        }
    } else {
        // ================= consumers (warps 0-6) =========================
        const int cix = warp * 32 + lane;  // 0..223 -> one float4 per stream
        int s = 0, ph = 0;
        for (int k = 0; k < cnt; ++k) {
            mbar_wait_acq(smem_u32(&s_full[s]), (uint32_t)ph);
            float4 o = ((const float4*)&s_o[s][0])[cix];
            float4 t = ((const float4*)&s_t[s][0])[cix];
            sum += quad_val(o, t);
            __syncwarp();                  // whole warp done reading stage s
            if (lane == 0) mbar_arrive(smem_u32(&s_empty[s]));
            if (++s == NSTG) { s = 0; ph ^= 1; }
        }
    }

    // ---- scalar tail over [ntiles*TILE_F, n) : all 256 threads ----
    for (int j = ntiles * TILE_F + bid * NTH + tid; j < n; j += G * NTH)
        sum += elem_val(out[j], tgt[j]);

    // ---- block reduce (full-warp shuffles only) ----
    #pragma unroll
    for (int off = 16; off > 0; off >>= 1)
        sum += __shfl_down_sync(0xFFFFFFFFu, sum, off);
    if (lane == 0) s_warp[warp] = sum;
    __syncthreads();

    if (warp == 0) {                      // full warp active
        float v = (lane < NTH / 32) ? s_warp[lane] : 0.0f;
        #pragma unroll
        for (int off = 16; off > 0; off >>= 1)
            v += __shfl_down_sync(0xFFFFFFFFu, v, off);
        if (lane == 0) {
            g_part[bid] = v;
            __threadfence();                                   // release
            unsigned int prev = atomicInc(&g_count, NBLK - 1u); // wraps -> 0
            s_last = (prev == NBLK - 1u);
        }
    }
    __syncthreads();

    if (s_last) {
        __threadfence();                  // acquire before reading g_part
        double acc = 0.0;                 // fixed-order deterministic reduce
        for (int k = tid; k < NBLK; k += NTH)
            acc += (double)g_part[k];

        #pragma unroll
        for (int off = 16; off > 0; off >>= 1)
            acc += __shfl_down_sync(0xFFFFFFFFu, acc, off);

        __shared__ double s_d[NTH / 32];
        if (lane == 0) s_d[warp] = acc;
        __syncthreads();

        if (warp == 0) {                  // full warp active
            double v = (lane < NTH / 32) ? s_d[lane] : 0.0;
            #pragma unroll
            for (int off = 16; off > 0; off >>= 1)
                v += __shfl_down_sync(0xFFFFFFFFu, v, off);
            if (lane == 0)
                result[0] = (float)(v / (double)n);
        }
    }
}

extern "C" void kernel_launch(void* const* d_in, const int* in_sizes, int n_in,
                              void* d_out, int out_size)
{
    const float* output = (const float*)d_in[0];
    const float* target = (const float*)d_in[1];
    const int n = in_sizes[0];

    loss_tma_ws_kernel<<<NBLK, NTH>>>(output, target, (float*)d_out, n);
}

// round 15
// speedup vs baseline: 1.0461x; 1.0461x over previous
#include <cuda_runtime.h>
#include <cuda_bf16.h>
#include <cstdint>

// Fused gamma-pdf-weighted MSE mean reduction — BALANCED warp-specialized
// hybrid: warps 0-6 stream 78.3% of bytes via LDG.256.cv (L1tex path, meas.
// 5.1 TB/s), warp 7 streams 21.7% via a private 4-stage TMA ring (meas.
// ~1.7 TB/s consume rate, LDS-issue-bound). R12 proved the two paths ADD
// (~6.8 TB/s in its overlap window); its failure was a 45% share on the
// TMA warp. This split equalizes finish times.
//
// math: mean( 0.5*(output-target)^2 * ef(target) )
// ef(y) = (BETA - c)*(1 - pdf(y)/FX_MAX) + c; pdf/FX_MAX < 4e-19 for fp32
// uniform targets except exact zeros -> log/exp only in cold branch.

#define NBLK    592          // 148 SMs * 4
#define NTH     256
#define LDG_NTH 224          // warps 0-6
#define TILE_F  1024         // floats per stream per TMA tile
#define TILE_B  (TILE_F * 4) // 4096 bytes
#define NSTG    4            // ring: 4 * 2 * 4KB = 32KB smem
#define TILES_PB 6           // TMA tiles per block -> 21.7% of n=2^24

__device__ float        g_part[NBLK];
__device__ unsigned int g_count;   // zero-init; self-resetting via atomicInc wrap

// ---------------- math ----------------
__device__ __forceinline__ float elem_val(float o, float y) {
    const float A1        = -0.9355570857535674f;            // EST_A - 1
    const float NEG_LOC   = 1.1328205299926424e-27f;         // -EST_LOC
    const float INV_SCALE = (float)(1.0 / 1.5376362609160314);
    const float C0        = -58.4492351f;                    // -lgamma(a)-ln(scale)-ln(FX_MAX)
    const float C         = (float)(1.0 / 107.2185);
    const float BC        = 5.0f - (float)(1.0 / 107.2185);

    float r = 0.0f;
    if (y < 1e-6f) {                      // cold path: only (near-)zero targets
        float x  = (y + NEG_LOC) * INV_SCALE;
        float lp = fmaf(A1, __logf(x), C0) - x;
        r = __expf(lp);
    }
    float ef   = fmaf(BC, 1.0f - r, C);
    float diff = o - y;
    return 0.5f * diff * diff * ef;
}

__device__ __forceinline__ void ldg256_cv(const float* __restrict__ p, float r[8]) {
    asm volatile("ld.global.cv.v8.f32 {%0,%1,%2,%3,%4,%5,%6,%7}, [%8];"
                 : "=f"(r[0]), "=f"(r[1]), "=f"(r[2]), "=f"(r[3]),
                   "=f"(r[4]), "=f"(r[5]), "=f"(r[6]), "=f"(r[7])
                 : "l"(p));
}

__device__ __forceinline__ float oct_val(const float o[8], const float t[8]) {
    float s = 0.0f;
    #pragma unroll
    for (int j = 0; j < 8; ++j) s += elem_val(o[j], t[j]);
    return s;
}

__device__ __forceinline__ float quad_val(float4 o, float4 t) {
    return elem_val(o.x, t.x) + elem_val(o.y, t.y)
         + elem_val(o.z, t.z) + elem_val(o.w, t.w);
}

// ---------------- PTX helpers ----------------
__device__ __forceinline__ uint32_t smem_u32(const void* p) {
    uint32_t a;
    asm("{ .reg .u64 t; cvta.to.shared.u64 t, %1; cvt.u32.u64 %0, t; }"
        : "=r"(a) : "l"(p));
    return a;
}
__device__ __forceinline__ void mbar_init(uint32_t mbar, uint32_t count) {
    asm volatile("mbarrier.init.shared.b64 [%0], %1;"
                 :: "r"(mbar), "r"(count) : "memory");
}
__device__ __forceinline__ void mbar_expect_tx(uint32_t mbar, uint32_t bytes) {
    asm volatile("mbarrier.arrive.expect_tx.shared.b64 _, [%0], %1;"
                 :: "r"(mbar), "r"(bytes) : "memory");
}
__device__ __forceinline__ void mbar_wait_acq(uint32_t mbar, uint32_t parity) {
    uint32_t done;
    do {
        asm volatile(
            "{ .reg .pred p;\n"
            "  mbarrier.try_wait.parity.acquire.cta.shared::cta.b64 p, [%1], %2, 0x989680;\n"
            "  selp.b32 %0, 1, 0, p; }"
            : "=r"(done) : "r"(mbar), "r"(parity) : "memory");
    } while (!done);
}
__device__ __forceinline__ void bulk_ld(uint32_t dst, const float* src,
                                        uint32_t bytes, uint32_t mbar) {
    asm volatile(
        "cp.async.bulk.shared::cluster.global.mbarrier::complete_tx::bytes "
        "[%0], [%1], %2, [%3];"
        :: "r"(dst), "l"(src), "r"(bytes), "r"(mbar) : "memory");
}
__device__ __forceinline__ void fence_proxy_async_shared() {
    asm volatile("fence.proxy.async.shared::cta;" ::: "memory");
}

// ---------------- kernel ----------------
// P        : floats on the LDG path (prefix); TMA covers [P, P + NBLK*tiles_pb*TILE_F)
__global__ __launch_bounds__(NTH) void loss_hybrid2_kernel(
    const float* __restrict__ out, const float* __restrict__ tgt,
    float* __restrict__ result, int n, int P, int tiles_pb)
{
    __shared__ alignas(16) float    s_o[NSTG][TILE_F];
    __shared__ alignas(16) float    s_t[NSTG][TILE_F];
    __shared__ alignas(8)  uint64_t s_mbar[NSTG];
    __shared__ float s_warp[NTH / 32];
    __shared__ bool  s_last;

    const int tid  = threadIdx.x;
    const int lane = tid & 31;
    const int warp = tid >> 5;
    const int bid  = blockIdx.x;

    float sum = 0.0f;

    if (warp == 7) {
        // ========== TMA path: single warp, private 4-stage ring ==========
        uint32_t mb[NSTG];
        #pragma unroll
        for (int s = 0; s < NSTG; ++s) mb[s] = smem_u32(&s_mbar[s]);

        if (lane == 0) {
            #pragma unroll
            for (int s = 0; s < NSTG; ++s) mbar_init(mb[s], 1);
            fence_proxy_async_shared();
        }
        __syncwarp();

        const long long tile0 = (long long)bid * tiles_pb;

        if (lane == 0) {                    // prologue: fill ring
            for (int k = 0; k < NSTG && k < tiles_pb; ++k) {
                const float* po = out + (size_t)P + (size_t)(tile0 + k) * TILE_F;
                const float* pt = tgt + (size_t)P + (size_t)(tile0 + k) * TILE_F;
                mbar_expect_tx(mb[k], 2 * TILE_B);
                bulk_ld(smem_u32(&s_o[k][0]), po, TILE_B, mb[k]);
                bulk_ld(smem_u32(&s_t[k][0]), pt, TILE_B, mb[k]);
            }
        }
        __syncwarp();

        for (int k = 0; k < tiles_pb; ++k) {
            const int s  = k & (NSTG - 1);
            const int ph = (k >> 2) & 1;
            mbar_wait_acq(mb[s], (uint32_t)ph);   // all 32 lanes

            const float4* so = (const float4*)&s_o[s][0];
            const float4* st = (const float4*)&s_t[s][0];
            #pragma unroll
            for (int j = 0; j < TILE_F / 4 / 32; ++j) {   // 8 float4/lane
                int id = lane + j * 32;
                sum += quad_val(so[id], st[id]);
            }
            __syncwarp();                   // warp done reading stage s

            if (lane == 0 && k + NSTG < tiles_pb) {
                const float* po = out + (size_t)P + (size_t)(tile0 + k + NSTG) * TILE_F;
                const float* pt = tgt + (size_t)P + (size_t)(tile0 + k + NSTG) * TILE_F;
                mbar_expect_tx(mb[s], 2 * TILE_B);
                bulk_ld(smem_u32(&s_o[s][0]), po, TILE_B, mb[s]);
                bulk_ld(smem_u32(&s_t[s][0]), pt, TILE_B, mb[s]);
            }
            __syncwarp();
        }
    } else {
        // ========== LDG path (warps 0-6, .cv 256-bit, unroll-2) ==========
        const int idx    = bid * LDG_NTH + tid;
        const int stride = NBLK * LDG_NTH;
        const int p8     = P >> 3;

        int i = idx;
        for (; i + stride < p8; i += 2 * stride) {
            float o0[8], t0[8], o1[8], t1[8];
            ldg256_cv(out + (size_t)i * 8,            o0);
            ldg256_cv(tgt + (size_t)i * 8,            t0);
            ldg256_cv(out + (size_t)(i + stride) * 8, o1);
            ldg256_cv(tgt + (size_t)(i + stride) * 8, t1);
            sum += oct_val(o0, t0);
            sum += oct_val(o1, t1);
        }
        for (; i < p8; i += stride) {
            float o0[8], t0[8];
            ldg256_cv(out + (size_t)i * 8, o0);
            ldg256_cv(tgt + (size_t)i * 8, t0);
            sum += oct_val(o0, t0);
        }
        for (int j = (p8 << 3) + idx; j < P; j += stride)   // P%8 tail
            sum += elem_val(out[j], tgt[j]);
        // floats beyond the TMA span (none when host sizes exactly)
        const int tma_end = P + NBLK * tiles_pb * TILE_F;
        for (int j = tma_end + idx; j < n; j += stride)
            sum += elem_val(out[j], tgt[j]);
    }

    // ---- block reduce over all 8 warps (full-warp shuffles only) ----
    #pragma unroll
    for (int off = 16; off > 0; off >>= 1)
        sum += __shfl_down_sync(0xFFFFFFFFu, sum, off);
    if (lane == 0) s_warp[warp] = sum;
    __syncthreads();

    if (warp == 0) {                      // full warp active
        float v = (lane < NTH / 32) ? s_warp[lane] : 0.0f;
        #pragma unroll
        for (int off = 16; off > 0; off >>= 1)
            v += __shfl_down_sync(0xFFFFFFFFu, v, off);
        if (lane == 0) {
            g_part[bid] = v;
            __threadfence();                                   // release
            unsigned int prev = atomicInc(&g_count, NBLK - 1u); // wraps -> 0
            s_last = (prev == NBLK - 1u);
        }
    }
    __syncthreads();

    if (s_last) {
        __threadfence();                  // acquire before reading g_part
        double acc = 0.0;                 // fixed-order deterministic reduce
        for (int k = tid; k < NBLK; k += NTH)
            acc += (double)g_part[k];

        #pragma unroll
        for (int off = 16; off > 0; off >>= 1)
            acc += __shfl_down_sync(0xFFFFFFFFu, acc, off);

        __shared__ double s_d[NTH / 32];
        if (lane == 0) s_d[warp] = acc;
        __syncthreads();

        if (warp == 0) {                  // full warp active
            double v = (lane < NTH / 32) ? s_d[lane] : 0.0;
            #pragma unroll
            for (int off = 16; off > 0; off >>= 1)
                v += __shfl_down_sync(0xFFFFFFFFu, v, off);
            if (lane == 0)
                result[0] = (float)(v / (double)n);
        }
    }
}

extern "C" void kernel_launch(void* const* d_in, const int* in_sizes, int n_in,
                              void* d_out, int out_size)
{
    const float* output = (const float*)d_in[0];
    const float* target = (const float*)d_in[1];
    const int n = in_sizes[0];

    // TMA share: TILES_PB whole tiles per block if they fit and alignment
    // holds (tile bases 16B-aligned -> P multiple of 4).
    int tiles_pb = 0;
    long long span = (long long)NBLK * TILES_PB * TILE_F;
    if ((n & 3) == 0 && span <= (long long)n * 3 / 4 + span) { /* always true */ }
    if ((n & 3) == 0 && span < n) tiles_pb = TILES_PB;
    int P = n - NBLK * tiles_pb * TILE_F;

    loss_hybrid2_kernel<<<NBLK, NTH>>>(output, target, (float*)d_out,
                                       n, P, tiles_pb);
}